// round 3
// baseline (speedup 1.0000x reference)
#include <cuda_runtime.h>

// Sequential scan: net_{i+1} = sigmoid(10*(net_i + u_i - 0.5)) componentwise (3 comps),
// pred_i = x_i . net_{i+1}, u_i = W x_i + b.
// Parallelized via chunked scan + warm-up: contraction of the sigmoid map kills
// dependence on chunk-entry state within ~30 steps; we warm up 96 steps from y=0.5.

#define B_ELEMS   4194304
#define L_CHUNK   256
#define N_CHUNKS  (B_ELEMS / L_CHUNK)      // 16384
#define THREADS   64
#define CPB       64                        // chunks per block (== THREADS)
#define NBLOCKS   (N_CHUNKS / CPB)          // 256
#define T_TILE    32
#define WARM      96
#define N_WARM_T  (WARM / T_TILE)           // 3
#define N_MAIN_T  (L_CHUNK / T_TILE)        // 8
#define ROWF      (3 * T_TILE)              // 96 floats of x per row-tile
#define ROWSTRIDE 97                        // +1 pad -> conflict-free LDS

__device__ __forceinline__ float fast_sigmoid(float z) {
    // 1/(1+e^-z); MUFU EX2 + MUFU RCP, ~1e-6 rel err, saturates correctly at +-inf
    return __fdividef(1.0f, 1.0f + __expf(-z));
}

__global__ __launch_bounds__(THREADS)
void updater_kernel(const float* __restrict__ x,
                    const float* __restrict__ Wm,
                    const float* __restrict__ bv,
                    const float* __restrict__ n0,
                    float* __restrict__ out)
{
    __shared__ float sx[CPB][ROWSTRIDE];

    const int tid    = threadIdx.x;
    const int blk_c0 = blockIdx.x * CPB;     // first chunk of this block
    const int c      = blk_c0 + tid;         // my chunk

    // broadcast params (L1-cached)
    const float w00 = Wm[0], w01 = Wm[1], w02 = Wm[2];
    const float w10 = Wm[3], w11 = Wm[4], w12 = Wm[5];
    const float w20 = Wm[6], w21 = Wm[7], w22 = Wm[8];
    const float b0 = bv[0], b1 = bv[1], b2 = bv[2];

    float y0, y1, y2;
    if (c == 0) { y0 = n0[0]; y1 = n0[1]; y2 = n0[2]; }
    else        { y0 = 0.5f;  y1 = 0.5f;  y2 = 0.5f; }

    for (int tile = 0; tile < N_WARM_T + N_MAIN_T; ++tile) {
        const int s0 = (tile - N_WARM_T) * T_TILE;   // uniform across block

        __syncthreads();  // prior store-phase reads done before we overwrite smem

        // ---- stage tile: 64 rows x 96 floats, coalesced ----
        {
            const int gbase = 3 * (blk_c0 * L_CHUNK + s0);
            for (int i = tid; i < CPB * ROWF; i += THREADS) {
                const int r   = i / ROWF;
                const int col = i - r * ROWF;
                int src = gbase + r * (3 * L_CHUNK) + col;   // only block 0 can go <0
                if (src < 0) src = 0;
                sx[r][col] = x[src];
            }
        }
        __syncthreads();

        // ---- compute: each thread walks its own row (conflict-free: stride 97) ----
        {
            float* row = sx[tid];
            const bool skip_all = (c == 0) && (s0 < 0);   // chunk 0 has exact init
            const bool is_main  = (s0 >= 0);
            if (!skip_all) {
                #pragma unroll
                for (int k = 0; k < T_TILE; ++k) {
                    const float xa = row[3 * k + 0];
                    const float xb = row[3 * k + 1];
                    const float xc = row[3 * k + 2];
                    const float u0 = fmaf(xc, w02, fmaf(xb, w01, fmaf(xa, w00, b0)));
                    const float u1 = fmaf(xc, w12, fmaf(xb, w11, fmaf(xa, w10, b1)));
                    const float u2 = fmaf(xc, w22, fmaf(xb, w21, fmaf(xa, w20, b2)));
                    y0 = fast_sigmoid(fmaf(y0 + u0, 10.0f, -5.0f));
                    y1 = fast_sigmoid(fmaf(y1 + u1, 10.0f, -5.0f));
                    y2 = fast_sigmoid(fmaf(y2 + u2, 10.0f, -5.0f));
                    if (is_main) {
                        // pred uses UPDATED net; overwrite consumed x slot with pred
                        row[3 * k] = fmaf(xc, y2, fmaf(xb, y1, xa * y0));
                    }
                }
            }
        }

        // ---- store tile: preds via smem, coalesced ----
        if (s0 >= 0) {
            __syncthreads();
            const int obase = blk_c0 * L_CHUNK + s0;
            for (int i = tid; i < CPB * T_TILE; i += THREADS) {
                const int r = i >> 5;           // /32
                const int k = i & 31;           // lane -> contiguous gmem
                out[obase + r * L_CHUNK + k] = sx[r][3 * k];  // banks 3k%32: distinct
            }
        }
    }
}

extern "C" void kernel_launch(void* const* d_in, const int* in_sizes, int n_in,
                              void* d_out, int out_size) {
    const float* x  = (const float*)d_in[0];   // (B,1,3)
    const float* Wm = (const float*)d_in[1];   // (3,3)
    const float* bv = (const float*)d_in[2];   // (3,)
    const float* n0 = (const float*)d_in[3];   // (3,1)
    float* out = (float*)d_out;                // (B,1)
    updater_kernel<<<NBLOCKS, THREADS>>>(x, Wm, bv, n0, out);
}

// round 5
// speedup vs baseline: 1.4314x; 1.4314x over previous
#include <cuda_runtime.h>

// Sequential scan: net_{i+1} = sigmoid(10*(net_i + u_i - 0.5)), pred_i = x_i . net_{i+1},
// u_i = W x_i + b. Chunked scan + warm-up (contraction ~2.5 nats/step kills entry-state
// dependence). R4: L=32, WARM=32 -> 131072 threads (8x parallelism vs R3, 1.45x work).

#define B_ELEMS   4194304
#define L_CHUNK   32
#define N_CHUNKS  (B_ELEMS / L_CHUNK)      // 131072
#define THREADS   128
#define CPB       128                       // chunks per block (== THREADS)
#define NBLOCKS   (N_CHUNKS / CPB)          // 1024
#define T_TILE    16
#define WARM      32
#define N_WARM_T  (WARM / T_TILE)           // 2
#define N_MAIN_T  (L_CHUNK / T_TILE)        // 2
#define ROWF      (3 * T_TILE)              // 48 floats of x per row-tile
#define ROWSTRIDE 49                        // +1 pad -> conflict-free LDS

// exp(-10*(y+u-0.5)) = 2^(A*y + v) with A = -10*log2(e), v = x.(A*W) + A*(b-0.5)
#define NEG10LOG2E (-14.4269504088896341f)

__device__ __forceinline__ float ex2_approx(float x) {
    float r; asm("ex2.approx.f32 %0, %1;" : "=f"(r) : "f"(x)); return r;
}
__device__ __forceinline__ float rcp_approx(float x) {
    float r; asm("rcp.approx.f32 %0, %1;" : "=f"(r) : "f"(x)); return r;
}

__global__ __launch_bounds__(THREADS, 8)
void updater_kernel(const float* __restrict__ x,
                    const float* __restrict__ Wm,
                    const float* __restrict__ bv,
                    const float* __restrict__ n0,
                    float* __restrict__ out)
{
    __shared__ float sx[CPB][ROWSTRIDE];

    const int tid    = threadIdx.x;
    const int blk_c0 = blockIdx.x * CPB;     // first chunk of this block
    const int c      = blk_c0 + tid;         // my chunk

    const float A = NEG10LOG2E;
    // pre-scaled weights: v = x . (A*W) + A*(b-0.5)
    const float w00 = A * Wm[0], w01 = A * Wm[1], w02 = A * Wm[2];
    const float w10 = A * Wm[3], w11 = A * Wm[4], w12 = A * Wm[5];
    const float w20 = A * Wm[6], w21 = A * Wm[7], w22 = A * Wm[8];
    const float b0 = A * (bv[0] - 0.5f);
    const float b1 = A * (bv[1] - 0.5f);
    const float b2 = A * (bv[2] - 0.5f);

    float y0, y1, y2;
    if (c == 0) { y0 = n0[0]; y1 = n0[1]; y2 = n0[2]; }
    else        { y0 = 0.5f;  y1 = 0.5f;  y2 = 0.5f; }

    #pragma unroll 1
    for (int tile = 0; tile < N_WARM_T + N_MAIN_T; ++tile) {
        const int s0 = (tile - N_WARM_T) * T_TILE;   // uniform across block

        __syncthreads();  // prior store-phase reads done before we overwrite smem

        // ---- stage tile: 128 rows x 48 floats, coalesced ----
        {
            const int gbase = 3 * (blk_c0 * L_CHUNK + s0);
            #pragma unroll
            for (int j = 0; j < (CPB * ROWF) / THREADS; ++j) {
                const int i   = tid + j * THREADS;
                const int r   = i / ROWF;
                const int col = i - r * ROWF;
                int src = gbase + r * (3 * L_CHUNK) + col;   // only chunk 0 warm rows go <0
                if (src < 0) src = 0;
                sx[r][col] = x[src];
            }
        }
        __syncthreads();

        // ---- compute: each thread walks its own row (stride 49 -> conflict-free) ----
        {
            float* row = sx[tid];
            const bool skip_all = (c == 0) && (s0 < 0);   // chunk 0 has exact init
            const bool is_main  = (s0 >= 0);
            if (!skip_all) {
                #pragma unroll
                for (int k = 0; k < T_TILE; ++k) {
                    const float xa = row[3 * k + 0];
                    const float xb = row[3 * k + 1];
                    const float xc = row[3 * k + 2];
                    const float v0 = fmaf(xc, w02, fmaf(xb, w01, fmaf(xa, w00, b0)));
                    const float v1 = fmaf(xc, w12, fmaf(xb, w11, fmaf(xa, w10, b1)));
                    const float v2 = fmaf(xc, w22, fmaf(xb, w21, fmaf(xa, w20, b2)));
                    // y = 1 / (1 + 2^(A*y + v))
                    y0 = rcp_approx(1.0f + ex2_approx(fmaf(y0, A, v0)));
                    y1 = rcp_approx(1.0f + ex2_approx(fmaf(y1, A, v1)));
                    y2 = rcp_approx(1.0f + ex2_approx(fmaf(y2, A, v2)));
                    if (is_main) {
                        // pred uses UPDATED net; overwrite consumed x slot with pred
                        row[3 * k] = fmaf(xc, y2, fmaf(xb, y1, xa * y0));
                    }
                }
            }
        }

        // ---- store tile: preds via smem, coalesced ----
        if (s0 >= 0) {
            __syncthreads();
            const int obase = blk_c0 * L_CHUNK + s0;
            #pragma unroll
            for (int j = 0; j < (CPB * T_TILE) / THREADS; ++j) {
                const int i = tid + j * THREADS;
                const int r = i / T_TILE;
                const int k = i - r * T_TILE;
                out[obase + r * L_CHUNK + k] = sx[r][3 * k];
            }
        }
    }
}

extern "C" void kernel_launch(void* const* d_in, const int* in_sizes, int n_in,
                              void* d_out, int out_size) {
    const float* x  = (const float*)d_in[0];   // (B,1,3)
    const float* Wm = (const float*)d_in[1];   // (3,3)
    const float* bv = (const float*)d_in[2];   // (3,)
    const float* n0 = (const float*)d_in[3];   // (3,1)
    float* out = (float*)d_out;                // (B,1)
    updater_kernel<<<NBLOCKS, THREADS>>>(x, Wm, bv, n0, out);
}